// round 15
// baseline (speedup 1.0000x reference)
#include <cuda_runtime.h>

// EffectiveProbability: post = normalize(p * (CM @ c)) per pixel.
// Input row-normalizations cancel against the output normalization -> skipped.
//
// prior/current [8,21,512,512] f32, cm [21,21] f32, out [B*H*W,21] f32.
//
// FINAL (= R13, best measured: 82.3us total / 78.2us kernel, 6.24 TB/s =
// the demonstrated HBM ceiling; kernel time == 528MB traffic floor).
// Validated structure:
//  - CM in __constant__ -> uniform-port LDCU feeding FFMA: zero LSU/smem
//    traffic for the 441 matrix reads per pixel (the decisive win, R9).
//  - 1 pixel/thread, all 42 input loads front-batched as coalesced __ldcs
//    (single-touch, evict-first): full DRAM latency absorbed by MLP.
//  - normalize in registers; smem-staged tile flushed as float4 __stcs
//    (fully coalesced 128B stores, near-zero epilogue ALU).
//  - BLOCK=128: finest block-phase interleave that still gains (R13/R14 sweep).

#define NCLS 21
#define HWSHIFT 18              // H*W = 512*512 = 2^18
#define HWSZ (1 << HWSHIFT)
#define BLOCK 128

__constant__ float c_cm[NCLS * NCLS];

__global__ __launch_bounds__(BLOCK)
void eff_prob_kernel(const float* __restrict__ prior,
                     const float* __restrict__ current,
                     float* __restrict__ out,
                     int npix)
{
    __shared__ float s_out[BLOCK * NCLS];    // 10752 B, 16B-divisible

    const int tid = threadIdx.x;
    const int n = blockIdx.x * BLOCK + tid;
    if (n < npix) {
        const int b  = n >> HWSHIFT;
        const int hw = n & (HWSZ - 1);
        const size_t base = ((size_t)b * NCLS << HWSHIFT) + hw;
        const float* __restrict__ cp = current + base;
        const float* __restrict__ pp = prior + base;

        // Front-batched fully-coalesced streaming loads (single-touch data:
        // evict-first). Maximum MLP; no in-loop DRAM dependency.
        float cv[NCLS];
        #pragma unroll
        for (int j = 0; j < NCLS; j++) cv[j] = __ldcs(cp + ((size_t)j << HWSHIFT));
        float pv[NCLS];
        #pragma unroll
        for (int j = 0; j < NCLS; j++) pv[j] = __ldcs(pp + ((size_t)j << HWSHIFT));

        float post[NCLS];
        float acc = 0.0f;
        #pragma unroll
        for (int i = 0; i < NCLS; i++) {
            float s = 0.0f;
            #pragma unroll
            for (int j = 0; j < NCLS; j++)
                s = fmaf(c_cm[i * NCLS + j], cv[j], s);   // LDCU (uniform port) + FFMA
            const float t = pv[i] * s;
            post[i] = t;
            acc += t;
        }
        const float inv = 1.0f / acc;

        // Normalized values into smem staging.
        // Write stride 21 words across the warp: gcd(21,32)=1 -> conflict-free.
        #pragma unroll
        for (int i = 0; i < NCLS; i++)
            s_out[tid * NCLS + i] = post[i] * inv;
    }
    __syncthreads();

    // Vectorized flush: [BLOCK*21] floats = BLOCK*21/4 float4 groups.
    // Fully coalesced LDS.128 + STG.128, streaming stores.
    const int    valid   = min(BLOCK, npix - blockIdx.x * BLOCK);
    const size_t out_off = (size_t)blockIdx.x * BLOCK * NCLS;
    if (valid == BLOCK) {
        float4*       o4 = (float4*)(out + out_off);
        const float4* s4 = (const float4*)s_out;
        #pragma unroll
        for (int k = tid; k < BLOCK * NCLS / 4; k += BLOCK)
            __stcs(o4 + k, s4[k]);
    } else {
        // Tail (never taken for npix = 2^21): scalar flush.
        const int count = valid * NCLS;
        for (int k = tid; k < count; k += BLOCK)
            __stcs(out + out_off + k, s_out[k]);
    }
}

extern "C" void kernel_launch(void* const* d_in, const int* in_sizes, int n_in,
                              void* d_out, int out_size)
{
    const float* prior   = (const float*)d_in[0];
    const float* current = (const float*)d_in[1];
    const float* cm      = (const float*)d_in[2];
    float*       out     = (float*)d_out;

    // D2D copy into the constant bank; async -> graph-capturable memcpy node.
    cudaMemcpyToSymbolAsync(c_cm, cm, NCLS * NCLS * sizeof(float), 0,
                            cudaMemcpyDeviceToDevice, 0);

    const int npix = in_sizes[0] / NCLS;   // B*H*W
    const int grid = (npix + BLOCK - 1) / BLOCK;
    eff_prob_kernel<<<grid, BLOCK>>>(prior, current, out, npix);
}

// round 16
// speedup vs baseline: 1.0085x; 1.0085x over previous
#include <cuda_runtime.h>

// EffectiveProbability: post = normalize(p * (CM @ c)) per pixel.
// Input row-normalizations cancel against the output normalization -> skipped.
//
// prior/current [8,21,512,512] f32, cm [21,21] f32, out [B*H*W,21] f32.
//
// FINAL (= R13; best measured 82.3us total / 78.2us kernel; re-bench R15
// confirmed 77.9us kernel => at the 528MB traffic floor at the device's
// demonstrated 6.25 TB/s streaming ceiling).
// Validated structure:
//  - CM in __constant__ -> uniform-port LDCU feeding FFMA: zero LSU/smem
//    traffic for the 441 matrix reads per pixel (the decisive win, R9).
//  - 1 pixel/thread, all 42 input loads front-batched as coalesced __ldcs
//    (single-touch, evict-first): full DRAM latency absorbed by MLP.
//  - normalize in registers; smem-staged tile flushed as float4 __stcs
//    (fully coalesced 128B stores, near-zero epilogue ALU).
//  - BLOCK=128: finest block-phase interleave that still gains (R13/R14 sweep).

#define NCLS 21
#define HWSHIFT 18              // H*W = 512*512 = 2^18
#define HWSZ (1 << HWSHIFT)
#define BLOCK 128

__constant__ float c_cm[NCLS * NCLS];

__global__ __launch_bounds__(BLOCK)
void eff_prob_kernel(const float* __restrict__ prior,
                     const float* __restrict__ current,
                     float* __restrict__ out,
                     int npix)
{
    __shared__ float s_out[BLOCK * NCLS];    // 10752 B, 16B-divisible

    const int tid = threadIdx.x;
    const int n = blockIdx.x * BLOCK + tid;
    if (n < npix) {
        const int b  = n >> HWSHIFT;
        const int hw = n & (HWSZ - 1);
        const size_t base = ((size_t)b * NCLS << HWSHIFT) + hw;
        const float* __restrict__ cp = current + base;
        const float* __restrict__ pp = prior + base;

        // Front-batched fully-coalesced streaming loads (single-touch data:
        // evict-first). Maximum MLP; no in-loop DRAM dependency.
        float cv[NCLS];
        #pragma unroll
        for (int j = 0; j < NCLS; j++) cv[j] = __ldcs(cp + ((size_t)j << HWSHIFT));
        float pv[NCLS];
        #pragma unroll
        for (int j = 0; j < NCLS; j++) pv[j] = __ldcs(pp + ((size_t)j << HWSHIFT));

        float post[NCLS];
        float acc = 0.0f;
        #pragma unroll
        for (int i = 0; i < NCLS; i++) {
            float s = 0.0f;
            #pragma unroll
            for (int j = 0; j < NCLS; j++)
                s = fmaf(c_cm[i * NCLS + j], cv[j], s);   // LDCU (uniform port) + FFMA
            const float t = pv[i] * s;
            post[i] = t;
            acc += t;
        }
        const float inv = 1.0f / acc;

        // Normalized values into smem staging.
        // Write stride 21 words across the warp: gcd(21,32)=1 -> conflict-free.
        #pragma unroll
        for (int i = 0; i < NCLS; i++)
            s_out[tid * NCLS + i] = post[i] * inv;
    }
    __syncthreads();

    // Vectorized flush: [BLOCK*21] floats = BLOCK*21/4 float4 groups.
    // Fully coalesced LDS.128 + STG.128, streaming stores.
    const int    valid   = min(BLOCK, npix - blockIdx.x * BLOCK);
    const size_t out_off = (size_t)blockIdx.x * BLOCK * NCLS;
    if (valid == BLOCK) {
        float4*       o4 = (float4*)(out + out_off);
        const float4* s4 = (const float4*)s_out;
        #pragma unroll
        for (int k = tid; k < BLOCK * NCLS / 4; k += BLOCK)
            __stcs(o4 + k, s4[k]);
    } else {
        // Tail (never taken for npix = 2^21): scalar flush.
        const int count = valid * NCLS;
        for (int k = tid; k < count; k += BLOCK)
            __stcs(out + out_off + k, s_out[k]);
    }
}

extern "C" void kernel_launch(void* const* d_in, const int* in_sizes, int n_in,
                              void* d_out, int out_size)
{
    const float* prior   = (const float*)d_in[0];
    const float* current = (const float*)d_in[1];
    const float* cm      = (const float*)d_in[2];
    float*       out     = (float*)d_out;

    // D2D copy into the constant bank; async -> graph-capturable memcpy node.
    cudaMemcpyToSymbolAsync(c_cm, cm, NCLS * NCLS * sizeof(float), 0,
                            cudaMemcpyDeviceToDevice, 0);

    const int npix = in_sizes[0] / NCLS;   // B*H*W
    const int grid = (npix + BLOCK - 1) / BLOCK;
    eff_prob_kernel<<<grid, BLOCK>>>(prior, current, out, npix);
}

// round 17
// speedup vs baseline: 1.0120x; 1.0035x over previous
#include <cuda_runtime.h>

// EffectiveProbability: post = normalize(p * (CM @ c)) per pixel.
// Input row-normalizations cancel against the output normalization -> skipped.
//
// prior/current [8,21,512,512] f32, cm [21,21] f32, out [B*H*W,21] f32.
//
// FINAL (= R13; best measured 82.3us total / 78.2us kernel; re-benches R15/R16
// confirm 77.9-78.7us kernel = noise around the traffic floor: achieved
// 6.2-6.26 TB/s is the device ceiling for this stream, and measured bytes
// (~490MB) match the 528MB analytic minimum minus L2 absorption).
// Validated structure:
//  - CM in __constant__ -> uniform-port LDCU feeding FFMA: zero LSU/smem
//    traffic for the 441 matrix reads per pixel (the decisive win, R9: -26%).
//  - 1 pixel/thread, all 42 input loads front-batched as coalesced __ldcs
//    (single-touch, evict-first): full DRAM latency absorbed by MLP.
//  - normalize in registers; smem-staged tile flushed as float4 __stcs
//    (fully coalesced 128B stores, near-zero epilogue ALU).
//  - BLOCK=128: finest block-phase interleave that still gains (R13/R14 sweep).

#define NCLS 21
#define HWSHIFT 18              // H*W = 512*512 = 2^18
#define HWSZ (1 << HWSHIFT)
#define BLOCK 128

__constant__ float c_cm[NCLS * NCLS];

__global__ __launch_bounds__(BLOCK)
void eff_prob_kernel(const float* __restrict__ prior,
                     const float* __restrict__ current,
                     float* __restrict__ out,
                     int npix)
{
    __shared__ float s_out[BLOCK * NCLS];    // 10752 B, 16B-divisible

    const int tid = threadIdx.x;
    const int n = blockIdx.x * BLOCK + tid;
    if (n < npix) {
        const int b  = n >> HWSHIFT;
        const int hw = n & (HWSZ - 1);
        const size_t base = ((size_t)b * NCLS << HWSHIFT) + hw;
        const float* __restrict__ cp = current + base;
        const float* __restrict__ pp = prior + base;

        // Front-batched fully-coalesced streaming loads (single-touch data:
        // evict-first). Maximum MLP; no in-loop DRAM dependency.
        float cv[NCLS];
        #pragma unroll
        for (int j = 0; j < NCLS; j++) cv[j] = __ldcs(cp + ((size_t)j << HWSHIFT));
        float pv[NCLS];
        #pragma unroll
        for (int j = 0; j < NCLS; j++) pv[j] = __ldcs(pp + ((size_t)j << HWSHIFT));

        float post[NCLS];
        float acc = 0.0f;
        #pragma unroll
        for (int i = 0; i < NCLS; i++) {
            float s = 0.0f;
            #pragma unroll
            for (int j = 0; j < NCLS; j++)
                s = fmaf(c_cm[i * NCLS + j], cv[j], s);   // LDCU (uniform port) + FFMA
            const float t = pv[i] * s;
            post[i] = t;
            acc += t;
        }
        const float inv = 1.0f / acc;

        // Normalized values into smem staging.
        // Write stride 21 words across the warp: gcd(21,32)=1 -> conflict-free.
        #pragma unroll
        for (int i = 0; i < NCLS; i++)
            s_out[tid * NCLS + i] = post[i] * inv;
    }
    __syncthreads();

    // Vectorized flush: [BLOCK*21] floats = BLOCK*21/4 float4 groups.
    // Fully coalesced LDS.128 + STG.128, streaming stores.
    const int    valid   = min(BLOCK, npix - blockIdx.x * BLOCK);
    const size_t out_off = (size_t)blockIdx.x * BLOCK * NCLS;
    if (valid == BLOCK) {
        float4*       o4 = (float4*)(out + out_off);
        const float4* s4 = (const float4*)s_out;
        #pragma unroll
        for (int k = tid; k < BLOCK * NCLS / 4; k += BLOCK)
            __stcs(o4 + k, s4[k]);
    } else {
        // Tail (never taken for npix = 2^21): scalar flush.
        const int count = valid * NCLS;
        for (int k = tid; k < count; k += BLOCK)
            __stcs(out + out_off + k, s_out[k]);
    }
}

extern "C" void kernel_launch(void* const* d_in, const int* in_sizes, int n_in,
                              void* d_out, int out_size)
{
    const float* prior   = (const float*)d_in[0];
    const float* current = (const float*)d_in[1];
    const float* cm      = (const float*)d_in[2];
    float*       out     = (float*)d_out;

    // D2D copy into the constant bank; async -> graph-capturable memcpy node.
    cudaMemcpyToSymbolAsync(c_cm, cm, NCLS * NCLS * sizeof(float), 0,
                            cudaMemcpyDeviceToDevice, 0);

    const int npix = in_sizes[0] / NCLS;   // B*H*W
    const int grid = (npix + BLOCK - 1) / BLOCK;
    eff_prob_kernel<<<grid, BLOCK>>>(prior, current, out, npix);
}